// round 13
// baseline (speedup 1.0000x reference)
#include <cuda_runtime.h>
#include <cuda_bf16.h>
#include <cuda_fp16.h>
#include <cstdint>

#define N_TOK 1024
#define DH    64
#define NB    8
#define NGH   4
#define NLH   8
#define NLVL  4
#define NN    (N_TOK * N_TOK)
#define NBG   (NB * NGH)          // 32
#define KSTEPS 8                  // tf32 m16n8k8, K=64
#define SROWF  68                 // staging row stride in fp32 (272 B)
#define SBROW  136                // bounce row stride in half (272 B)
#define BG_PER_CTA 4              // bg planes per CTA (pipelined)

typedef unsigned long long u64t;

// ---------------- scratch ----------------
__device__ __half g_S[(size_t)NBG * NN];                      // 64 MB

__device__ __forceinline__ uint32_t smem_u32(const void* p) {
    uint32_t a;
    asm("{ .reg .u64 t; cvta.to.shared.u64 t, %1; cvt.u32.u64 %0, t; }" : "=r"(a) : "l"(p));
    return a;
}
__device__ __forceinline__ uint32_t f2tf32(float v) {
    uint32_t r; asm("cvt.rna.tf32.f32 %0, %1;" : "=r"(r) : "f"(v)); return r;
}

// ---------------- packed f32x2 helpers ----------------
__device__ __forceinline__ u64t pack2(float a, float b) {
    u64t r; asm("mov.b64 %0, {%1, %2};" : "=l"(r) : "f"(a), "f"(b)); return r;
}
__device__ __forceinline__ void unpack2(u64t p, float& a, float& b) {
    asm("mov.b64 {%0, %1}, %2;" : "=f"(a), "=f"(b) : "l"(p));
}
__device__ __forceinline__ u64t mul2(u64t a, u64t b) {
    u64t d; asm("mul.rn.f32x2 %0, %1, %2;" : "=l"(d) : "l"(a), "l"(b)); return d;
}
__device__ __forceinline__ u64t fma2(u64t a, u64t b, u64t c) {
    u64t d; asm("fma.rn.f32x2 %0, %1, %2, %3;" : "=l"(d) : "l"(a), "l"(b), "l"(c)); return d;
}

// ---------------------------------------------------------------------------
// Kernel 1: tf32 mma.sync GEMM, 4 bg planes per CTA, double-buffered staging
// with register prefetch (next plane's LDGs fly under current plane's MMAs).
// S stored via separate smem bounce -> coalesced STG.128.
// smem: 2 staging buffers (A|B each) + bounce = 174080 B.
// ---------------------------------------------------------------------------
#define STAGE_FLOATS (2 * 128 * SROWF)               // A|B, one buffer: 17408 floats
#define SM_TOTAL     (2 * STAGE_FLOATS * 4 + 128 * SBROW * 2)   // 174080

__global__ void qk_gemm_mma(const float* __restrict__ q, const float* __restrict__ k)
{
    extern __shared__ __align__(16) char smem[];
    float* stage = (float*)smem;                     // [2][STAGE_FLOATS]
    __half* Sb   = (__half*)(smem + 2 * STAGE_FLOATS * 4);   // bounce [128][SBROW]

    const int tid  = threadIdx.x;
    const int lane = tid & 31;
    const int w    = tid >> 5;
    const int wm   = (w & 1) * 64;
    const int wn   = (w >> 1) * 32;

    const int qt = blockIdx.y * 128;
    const int kt = blockIdx.x * 128;
    const int bg0 = blockIdx.z * BG_PER_CTA;

    // per-thread staging coordinates (fixed across iterations)
    int srow[8], sc4[8];
#pragma unroll
    for (int it = 0; it < 8; it++) {
        int idx = it * 256 + tid;
        srow[it] = idx >> 4;
        sc4[it]  = (idx & 15) * 4;
    }

    const int arow  = lane & 15;
    const int akoff = (lane >> 4) * 4;
    const int brow  = (lane & 7) + ((lane >> 4) << 3);
    const int bkoff = ((lane >> 3) & 1) * 4;

    // ---- prefetch plane 0 into registers ----
    float4 qreg[8], kreg[8];
    {
        const float* Qg = q + ((size_t)bg0 * N_TOK + qt) * DH;
        const float* Kg = k + ((size_t)bg0 * N_TOK + kt) * DH;
#pragma unroll
        for (int it = 0; it < 8; it++) {
            qreg[it] = *(const float4*)(Qg + (size_t)srow[it] * DH + sc4[it]);
            kreg[it] = *(const float4*)(Kg + (size_t)srow[it] * DH + sc4[it]);
        }
    }

#pragma unroll 1
    for (int t = 0; t < BG_PER_CTA; t++) {
        const int bgc = bg0 + t;
        float* As = stage + (t & 1) * STAGE_FLOATS;
        float* Bs = As + 128 * SROWF;

        // ---- cvt + STS current plane ----
#pragma unroll
        for (int it = 0; it < 8; it++) {
            *(uint4*)(As + srow[it] * SROWF + sc4[it]) =
                make_uint4(f2tf32(qreg[it].x), f2tf32(qreg[it].y),
                           f2tf32(qreg[it].z), f2tf32(qreg[it].w));
            *(uint4*)(Bs + srow[it] * SROWF + sc4[it]) =
                make_uint4(f2tf32(kreg[it].x), f2tf32(kreg[it].y),
                           f2tf32(kreg[it].z), f2tf32(kreg[it].w));
        }
        __syncthreads();

        // ---- prefetch next plane (LDGs fly under the MMA loop below) ----
        if (t + 1 < BG_PER_CTA) {
            const float* Qg = q + ((size_t)(bgc + 1) * N_TOK + qt) * DH;
            const float* Kg = k + ((size_t)(bgc + 1) * N_TOK + kt) * DH;
#pragma unroll
            for (int it = 0; it < 8; it++) {
                qreg[it] = *(const float4*)(Qg + (size_t)srow[it] * DH + sc4[it]);
                kreg[it] = *(const float4*)(Kg + (size_t)srow[it] * DH + sc4[it]);
            }
        }

        const uint32_t a_base = smem_u32(As);
        const uint32_t b_base = smem_u32(Bs);

        float acc[4][4][4];
#pragma unroll
        for (int mi = 0; mi < 4; mi++)
#pragma unroll
            for (int ni = 0; ni < 4; ni++)
#pragma unroll
                for (int r = 0; r < 4; r++) acc[mi][ni][r] = 0.0f;

#pragma unroll
        for (int s = 0; s < KSTEPS; s++) {
            const int k0 = s * 8;
            uint32_t af[4][4], bf[4][2];
#pragma unroll
            for (int mi = 0; mi < 4; mi++) {
                uint32_t addr = a_base + (uint32_t)(((wm + mi * 16 + arow) * SROWF + k0 + akoff) * 4);
                asm volatile("ldmatrix.sync.aligned.m8n8.x4.shared.b16 {%0,%1,%2,%3}, [%4];"
                             : "=r"(af[mi][0]), "=r"(af[mi][1]), "=r"(af[mi][2]), "=r"(af[mi][3])
                             : "r"(addr));
            }
#pragma unroll
            for (int nip = 0; nip < 2; nip++) {
                uint32_t addr = b_base + (uint32_t)(((wn + nip * 16 + brow) * SROWF + k0 + bkoff) * 4);
                asm volatile("ldmatrix.sync.aligned.m8n8.x4.shared.b16 {%0,%1,%2,%3}, [%4];"
                             : "=r"(bf[2 * nip][0]), "=r"(bf[2 * nip][1]),
                               "=r"(bf[2 * nip + 1][0]), "=r"(bf[2 * nip + 1][1])
                             : "r"(addr));
            }
#pragma unroll
            for (int mi = 0; mi < 4; mi++)
#pragma unroll
                for (int ni = 0; ni < 4; ni++) {
                    asm volatile(
                        "mma.sync.aligned.m16n8k8.row.col.f32.tf32.tf32.f32 "
                        "{%0,%1,%2,%3}, {%4,%5,%6,%7}, {%8,%9}, {%0,%1,%2,%3};"
                        : "+f"(acc[mi][ni][0]), "+f"(acc[mi][ni][1]),
                          "+f"(acc[mi][ni][2]), "+f"(acc[mi][ni][3])
                        : "r"(af[mi][0]), "r"(af[mi][1]), "r"(af[mi][2]), "r"(af[mi][3]),
                          "r"(bf[ni][0]), "r"(bf[ni][1]));
                }
        }

        // ---- bounce fragments -> smem (bounce region is private, no conflict
        //      with staging buffers; prev iter's STG reads finished at the
        //      loop-end sync) ----
#pragma unroll
        for (int mi = 0; mi < 4; mi++) {
#pragma unroll
            for (int ni = 0; ni < 4; ni++) {
                int m = wm + mi * 16 + (lane >> 2);
                int n = wn + ni * 8 + (lane & 3) * 2;
                *(__half2*)(Sb + m * SBROW + n) =
                    __floats2half2_rn(acc[mi][ni][0], acc[mi][ni][1]);
                *(__half2*)(Sb + (m + 8) * SBROW + n) =
                    __floats2half2_rn(acc[mi][ni][2], acc[mi][ni][3]);
            }
        }
        __syncthreads();

        // ---- coalesced STG.128 readout ----
        __half* __restrict__ Sp = g_S + (size_t)bgc * NN;
        const int rr = tid >> 4;
        const int cc = (tid & 15) * 8;
#pragma unroll
        for (int it = 0; it < 8; it++) {
            int row = it * 16 + rr;
            uint4 v = *(const uint4*)(Sb + row * SBROW + cc);
            *(uint4*)(Sp + (size_t)(qt + row) * N_TOK + kt + cc) = v;
        }
        __syncthreads();   // protect bounce (and staging buffer t&1) for reuse
    }
}

// ---------------------------------------------------------------------------
// Kernel 2: epilogue — EXACT Round-7 version (proven ~62-64 us).
// ---------------------------------------------------------------------------
__global__ __launch_bounds__(128, 3)
void epilogue_kernel(const float* __restrict__ masks,
                     const float* __restrict__ proj,   // [4][32]
                     const float* __restrict__ hw,     // [8][8]
                     const float* __restrict__ hb,     // [8]
                     float* __restrict__ out)
{
    __shared__ u64t sP2[64];
    __shared__ u64t sWt2[32];
    __shared__ u64t sB2[4];

    const int tid = threadIdx.x;
    if (tid < 64) {
        int l = tid >> 4, xp = tid & 15;
        sP2[tid] = pack2(proj[l * 32 + 2 * xp], proj[l * 32 + 2 * xp + 1]);
    }
    if (tid < 32) {
        int hh = tid >> 2, hp = tid & 3;
        sWt2[tid] = pack2(hw[(2 * hp) * 8 + hh], hw[(2 * hp + 1) * 8 + hh]);
    }
    if (tid < 4) sB2[tid] = pack2(hb[2 * tid], hb[2 * tid + 1]);
    __syncthreads();

    const size_t i0 = 2 * ((size_t)blockIdx.x * 128 + tid);
    const __half* __restrict__ Sp = g_S + i0;

    __half2 sh[NBG];
#pragma unroll
    for (int j = 0; j < NBG; j++) sh[j] = *(const __half2*)(Sp + ((size_t)j << 20));

    float4 ma = *(const float4*)(masks + 4 * i0);
    float4 mb = *(const float4*)(masks + 4 * i0 + 4);

    u64t mwA[16], mwB[16];
    {
        u64t ax = pack2(ma.x, ma.x), ay = pack2(ma.y, ma.y);
        u64t az = pack2(ma.z, ma.z), aw = pack2(ma.w, ma.w);
        u64t bx = pack2(mb.x, mb.x), by = pack2(mb.y, mb.y);
        u64t bz = pack2(mb.z, mb.z), bw = pack2(mb.w, mb.w);
#pragma unroll
        for (int xp = 0; xp < 16; xp++) {
            u64t p0 = sP2[xp], p1 = sP2[16 + xp], p2 = sP2[32 + xp], p3 = sP2[48 + xp];
            u64t tA = mul2(ax, p0);
            tA = fma2(ay, p1, tA);
            tA = fma2(az, p2, tA);
            tA = fma2(aw, p3, tA);
            mwA[xp] = tA;
            u64t tB = mul2(bx, p0);
            tB = fma2(by, p1, tB);
            tB = fma2(bz, p2, tB);
            tB = fma2(bw, p3, tB);
            mwB[xp] = tB;
        }
    }

#pragma unroll
    for (int b = 0; b < NB; b++) {
        float2 f0 = __half22float2(sh[b * 4 + 0]);
        float2 f1 = __half22float2(sh[b * 4 + 1]);
        float2 f2 = __half22float2(sh[b * 4 + 2]);
        float2 f3 = __half22float2(sh[b * 4 + 3]);

        u64t a0 = pack2(f0.x, f0.x), a1 = pack2(f1.x, f1.x);
        u64t a2 = pack2(f2.x, f2.x), a3 = pack2(f3.x, f3.x);
        u64t b0 = pack2(f0.y, f0.y), b1 = pack2(f1.y, f1.y);
        u64t b2 = pack2(f2.y, f2.y), b3 = pack2(f3.y, f3.y);

        u64t pvA[8], pvB[8];
#pragma unroll
        for (int hp = 0; hp < 4; hp++) {
            u64t tA = mul2(a0, mwA[hp]);
            tA = fma2(a1, mwA[4 + hp], tA);
            tA = fma2(a2, mwA[8 + hp], tA);
            tA = fma2(a3, mwA[12 + hp], tA);
            float vA0, vA1; unpack2(tA, vA0, vA1);
            vA0 = fmaxf(vA0, 0.0f); vA1 = fmaxf(vA1, 0.0f);
            pvA[2 * hp]     = pack2(vA0, vA0);
            pvA[2 * hp + 1] = pack2(vA1, vA1);

            u64t tB = mul2(b0, mwB[hp]);
            tB = fma2(b1, mwB[4 + hp], tB);
            tB = fma2(b2, mwB[8 + hp], tB);
            tB = fma2(b3, mwB[12 + hp], tB);
            float vB0, vB1; unpack2(tB, vB0, vB1);
            vB0 = fmaxf(vB0, 0.0f); vB1 = fmaxf(vB1, 0.0f);
            pvB[2 * hp]     = pack2(vB0, vB0);
            pvB[2 * hp + 1] = pack2(vB1, vB1);
        }

#pragma unroll
        for (int hp = 0; hp < 4; hp++) {
            u64t oA = sB2[hp], oB = sB2[hp];
#pragma unroll
            for (int hh = 0; hh < 8; hh++) {
                u64t wv = sWt2[hh * 4 + hp];
                oA = fma2(pvA[hh], wv, oA);
                oB = fma2(pvB[hh], wv, oB);
            }
            float oA0, oA1, oB0, oB1;
            unpack2(oA, oA0, oA1);
            unpack2(oB, oB0, oB1);
            *(float2*)(out + ((size_t)(b * 8 + 2 * hp)     << 20) + i0) = make_float2(oA0, oB0);
            *(float2*)(out + ((size_t)(b * 8 + 2 * hp + 1) << 20) + i0) = make_float2(oA1, oB1);
        }
    }
}

extern "C" void kernel_launch(void* const* d_in, const int* in_sizes, int n_in,
                              void* d_out, int out_size)
{
    const float* q     = (const float*)d_in[0];
    const float* k     = (const float*)d_in[1];
    const float* masks = (const float*)d_in[2];
    const float* proj  = (const float*)d_in[3];
    const float* hw    = (const float*)d_in[4];
    const float* hb    = (const float*)d_in[5];
    float* out = (float*)d_out;

    cudaFuncSetAttribute(qk_gemm_mma, cudaFuncAttributeMaxDynamicSharedMemorySize, SM_TOTAL);

    dim3 g1(N_TOK / 128, N_TOK / 128, NBG / BG_PER_CTA);   // (8,8,8)
    qk_gemm_mma<<<g1, 256, SM_TOTAL>>>(q, k);

    epilogue_kernel<<<NN / 256, 128>>>(masks, proj, hw, hb, out);
}

// round 14
// speedup vs baseline: 1.2240x; 1.2240x over previous
#include <cuda_runtime.h>
#include <cuda_bf16.h>
#include <cuda_fp16.h>
#include <cstdint>

#define N_TOK 1024
#define DH    64
#define NB    8
#define NGH   4
#define NLH   8
#define NLVL  4
#define NN    (N_TOK * N_TOK)
#define NBG   (NB * NGH)          // 32
#define KSTEPS 8                  // tf32 m16n8k8, K=64
#define SROWF  68                 // staging row stride in fp32 (272 B)
#define SBROW  136                // bounce row stride in half (272 B)

typedef unsigned long long u64t;

// ---------------- scratch ----------------
__device__ __half g_S[(size_t)NBG * NN];                      // 64 MB

__device__ __forceinline__ uint32_t smem_u32(const void* p) {
    uint32_t a;
    asm("{ .reg .u64 t; cvta.to.shared.u64 t, %1; cvt.u32.u64 %0, t; }" : "=r"(a) : "l"(p));
    return a;
}
__device__ __forceinline__ uint32_t f2tf32(float v) {
    uint32_t r; asm("cvt.rna.tf32.f32 %0, %1;" : "=r"(r) : "f"(v)); return r;
}

// ---------------- packed f32x2 helpers ----------------
__device__ __forceinline__ u64t pack2(float a, float b) {
    u64t r; asm("mov.b64 %0, {%1, %2};" : "=l"(r) : "f"(a), "f"(b)); return r;
}
__device__ __forceinline__ void unpack2(u64t p, float& a, float& b) {
    asm("mov.b64 {%0, %1}, %2;" : "=f"(a), "=f"(b) : "l"(p));
}
__device__ __forceinline__ u64t mul2(u64t a, u64t b) {
    u64t d; asm("mul.rn.f32x2 %0, %1, %2;" : "=l"(d) : "l"(a), "l"(b)); return d;
}
__device__ __forceinline__ u64t fma2(u64t a, u64t b, u64t c) {
    u64t d; asm("fma.rn.f32x2 %0, %1, %2, %3;" : "=l"(d) : "l"(a), "l"(b), "l"(c)); return d;
}

// streaming (evict-first) memory ops
__device__ __forceinline__ uint32_t ldcs_u32(const void* p) {
    uint32_t v; asm volatile("ld.global.cs.b32 %0, [%1];" : "=r"(v) : "l"(p)); return v;
}
__device__ __forceinline__ float4 ldcs_f4(const void* p) {
    float4 v;
    asm volatile("ld.global.cs.v4.f32 {%0,%1,%2,%3}, [%4];"
                 : "=f"(v.x), "=f"(v.y), "=f"(v.z), "=f"(v.w) : "l"(p));
    return v;
}
__device__ __forceinline__ void stcs_u64(void* p, u64t v) {
    asm volatile("st.global.cs.b64 [%0], %1;" :: "l"(p), "l"(v) : "memory");
}

// ---------------------------------------------------------------------------
// Kernel 1: tf32 mma.sync GEMM (m16n8k8), K=64 — EXACT Round-12 version
// (proven ~35 us: 69.6 KB smem -> 2 CTAs/SM give inter-CTA overlap).
// ---------------------------------------------------------------------------
#define SM_BYTES (2 * 128 * SROWF * 4)    // 69632

__global__ __launch_bounds__(256)
void qk_gemm_mma(const float* __restrict__ q, const float* __restrict__ k)
{
    extern __shared__ __align__(16) char smem[];
    float* As = (float*)smem;               // [128][SROWF]
    float* Bs = As + 128 * SROWF;

    const int tid  = threadIdx.x;
    const int lane = tid & 31;
    const int w    = tid >> 5;
    const int wm   = (w & 1) * 64;
    const int wn   = (w >> 1) * 32;

    const int bg = blockIdx.z;
    const int qt = blockIdx.y * 128;
    const int kt = blockIdx.x * 128;

    const float* Qg = q + ((size_t)bg * N_TOK + qt) * DH;
    const float* Kg = k + ((size_t)bg * N_TOK + kt) * DH;

#pragma unroll
    for (int it = 0; it < 8; it++) {
        int idx = it * 256 + tid;
        int row = idx >> 4;
        int c4  = (idx & 15) * 4;
        float4 qv = *(const float4*)(Qg + (size_t)row * DH + c4);
        float4 kv = *(const float4*)(Kg + (size_t)row * DH + c4);
        *(uint4*)(As + row * SROWF + c4) =
            make_uint4(f2tf32(qv.x), f2tf32(qv.y), f2tf32(qv.z), f2tf32(qv.w));
        *(uint4*)(Bs + row * SROWF + c4) =
            make_uint4(f2tf32(kv.x), f2tf32(kv.y), f2tf32(kv.z), f2tf32(kv.w));
    }
    __syncthreads();

    const uint32_t a_base = smem_u32(As);
    const uint32_t b_base = smem_u32(Bs);

    const int arow  = lane & 15;
    const int akoff = (lane >> 4) * 4;
    const int brow  = (lane & 7) + ((lane >> 4) << 3);
    const int bkoff = ((lane >> 3) & 1) * 4;

    float acc[4][4][4];
#pragma unroll
    for (int mi = 0; mi < 4; mi++)
#pragma unroll
        for (int ni = 0; ni < 4; ni++)
#pragma unroll
            for (int r = 0; r < 4; r++) acc[mi][ni][r] = 0.0f;

#pragma unroll
    for (int s = 0; s < KSTEPS; s++) {
        const int k0 = s * 8;

        uint32_t af[4][4], bf[4][2];
#pragma unroll
        for (int mi = 0; mi < 4; mi++) {
            uint32_t addr = a_base + (uint32_t)(((wm + mi * 16 + arow) * SROWF + k0 + akoff) * 4);
            asm volatile("ldmatrix.sync.aligned.m8n8.x4.shared.b16 {%0,%1,%2,%3}, [%4];"
                         : "=r"(af[mi][0]), "=r"(af[mi][1]), "=r"(af[mi][2]), "=r"(af[mi][3])
                         : "r"(addr));
        }
#pragma unroll
        for (int nip = 0; nip < 2; nip++) {
            uint32_t addr = b_base + (uint32_t)(((wn + nip * 16 + brow) * SROWF + k0 + bkoff) * 4);
            asm volatile("ldmatrix.sync.aligned.m8n8.x4.shared.b16 {%0,%1,%2,%3}, [%4];"
                         : "=r"(bf[2 * nip][0]), "=r"(bf[2 * nip][1]),
                           "=r"(bf[2 * nip + 1][0]), "=r"(bf[2 * nip + 1][1])
                         : "r"(addr));
        }
#pragma unroll
        for (int mi = 0; mi < 4; mi++)
#pragma unroll
            for (int ni = 0; ni < 4; ni++) {
                asm volatile(
                    "mma.sync.aligned.m16n8k8.row.col.f32.tf32.tf32.f32 "
                    "{%0,%1,%2,%3}, {%4,%5,%6,%7}, {%8,%9}, {%0,%1,%2,%3};"
                    : "+f"(acc[mi][ni][0]), "+f"(acc[mi][ni][1]),
                      "+f"(acc[mi][ni][2]), "+f"(acc[mi][ni][3])
                    : "r"(af[mi][0]), "r"(af[mi][1]), "r"(af[mi][2]), "r"(af[mi][3]),
                      "r"(bf[ni][0]), "r"(bf[ni][1]));
            }
    }

    // --- bounce: fragments -> smem (conflict-free STS.32) ---
    __syncthreads();
    __half* Sb = (__half*)smem;           // [128][SBROW]
#pragma unroll
    for (int mi = 0; mi < 4; mi++) {
#pragma unroll
        for (int ni = 0; ni < 4; ni++) {
            int m = wm + mi * 16 + (lane >> 2);
            int n = wn + ni * 8 + (lane & 3) * 2;
            *(__half2*)(Sb + m * SBROW + n) =
                __floats2half2_rn(acc[mi][ni][0], acc[mi][ni][1]);
            *(__half2*)(Sb + (m + 8) * SBROW + n) =
                __floats2half2_rn(acc[mi][ni][2], acc[mi][ni][3]);
        }
    }
    __syncthreads();

    // --- readout: coalesced STG.128 (default policy: keep S in L2) ---
    __half* __restrict__ Sp = g_S + (size_t)bg * NN;
    const int rr = tid >> 4;
    const int cc = (tid & 15) * 8;
#pragma unroll
    for (int it = 0; it < 8; it++) {
        int row = it * 16 + rr;
        uint4 v = *(const uint4*)(Sb + row * SBROW + cc);
        *(uint4*)(Sp + (size_t)(qt + row) * N_TOK + kt + cc) = v;
    }
}

// ---------------------------------------------------------------------------
// Kernel 2: epilogue — R7 structure + streaming cache hints:
//   S loads .cs (read-once), masks .cs (read-once), out stores .cs
//   (evict-first) so the 256 MB out stream doesn't evict S from L2.
// ---------------------------------------------------------------------------
__global__ __launch_bounds__(128, 3)
void epilogue_kernel(const float* __restrict__ masks,
                     const float* __restrict__ proj,   // [4][32]
                     const float* __restrict__ hw,     // [8][8]
                     const float* __restrict__ hb,     // [8]
                     float* __restrict__ out)
{
    __shared__ u64t sP2[64];
    __shared__ u64t sWt2[32];
    __shared__ u64t sB2[4];

    const int tid = threadIdx.x;
    if (tid < 64) {
        int l = tid >> 4, xp = tid & 15;
        sP2[tid] = pack2(proj[l * 32 + 2 * xp], proj[l * 32 + 2 * xp + 1]);
    }
    if (tid < 32) {
        int hh = tid >> 2, hp = tid & 3;
        sWt2[tid] = pack2(hw[(2 * hp) * 8 + hh], hw[(2 * hp + 1) * 8 + hh]);
    }
    if (tid < 4) sB2[tid] = pack2(hb[2 * tid], hb[2 * tid + 1]);
    __syncthreads();

    const size_t i0 = 2 * ((size_t)blockIdx.x * 128 + tid);
    const __half* __restrict__ Sp = g_S + i0;

    // 32 independent streaming S loads (read-once), issued up front
    __half2 sh[NBG];
#pragma unroll
    for (int j = 0; j < NBG; j++) {
        uint32_t bits = ldcs_u32(Sp + ((size_t)j << 20));
        sh[j] = *(__half2*)&bits;
    }

    float4 ma = ldcs_f4(masks + 4 * i0);
    float4 mb = ldcs_f4(masks + 4 * i0 + 4);

    u64t mwA[16], mwB[16];
    {
        u64t ax = pack2(ma.x, ma.x), ay = pack2(ma.y, ma.y);
        u64t az = pack2(ma.z, ma.z), aw = pack2(ma.w, ma.w);
        u64t bx = pack2(mb.x, mb.x), by = pack2(mb.y, mb.y);
        u64t bz = pack2(mb.z, mb.z), bw = pack2(mb.w, mb.w);
#pragma unroll
        for (int xp = 0; xp < 16; xp++) {
            u64t p0 = sP2[xp], p1 = sP2[16 + xp], p2 = sP2[32 + xp], p3 = sP2[48 + xp];
            u64t tA = mul2(ax, p0);
            tA = fma2(ay, p1, tA);
            tA = fma2(az, p2, tA);
            tA = fma2(aw, p3, tA);
            mwA[xp] = tA;
            u64t tB = mul2(bx, p0);
            tB = fma2(by, p1, tB);
            tB = fma2(bz, p2, tB);
            tB = fma2(bw, p3, tB);
            mwB[xp] = tB;
        }
    }

#pragma unroll
    for (int b = 0; b < NB; b++) {
        float2 f0 = __half22float2(sh[b * 4 + 0]);
        float2 f1 = __half22float2(sh[b * 4 + 1]);
        float2 f2 = __half22float2(sh[b * 4 + 2]);
        float2 f3 = __half22float2(sh[b * 4 + 3]);

        u64t a0 = pack2(f0.x, f0.x), a1 = pack2(f1.x, f1.x);
        u64t a2 = pack2(f2.x, f2.x), a3 = pack2(f3.x, f3.x);
        u64t b0 = pack2(f0.y, f0.y), b1 = pack2(f1.y, f1.y);
        u64t b2 = pack2(f2.y, f2.y), b3 = pack2(f3.y, f3.y);

        u64t pvA[8], pvB[8];
#pragma unroll
        for (int hp = 0; hp < 4; hp++) {
            u64t tA = mul2(a0, mwA[hp]);
            tA = fma2(a1, mwA[4 + hp], tA);
            tA = fma2(a2, mwA[8 + hp], tA);
            tA = fma2(a3, mwA[12 + hp], tA);
            float vA0, vA1; unpack2(tA, vA0, vA1);
            vA0 = fmaxf(vA0, 0.0f); vA1 = fmaxf(vA1, 0.0f);
            pvA[2 * hp]     = pack2(vA0, vA0);
            pvA[2 * hp + 1] = pack2(vA1, vA1);

            u64t tB = mul2(b0, mwB[hp]);
            tB = fma2(b1, mwB[4 + hp], tB);
            tB = fma2(b2, mwB[8 + hp], tB);
            tB = fma2(b3, mwB[12 + hp], tB);
            float vB0, vB1; unpack2(tB, vB0, vB1);
            vB0 = fmaxf(vB0, 0.0f); vB1 = fmaxf(vB1, 0.0f);
            pvB[2 * hp]     = pack2(vB0, vB0);
            pvB[2 * hp + 1] = pack2(vB1, vB1);
        }

#pragma unroll
        for (int hp = 0; hp < 4; hp++) {
            u64t oA = sB2[hp], oB = sB2[hp];
#pragma unroll
            for (int hh = 0; hh < 8; hh++) {
                u64t wv = sWt2[hh * 4 + hp];
                oA = fma2(pvA[hh], wv, oA);
                oB = fma2(pvB[hh], wv, oB);
            }
            float oA0, oA1, oB0, oB1;
            unpack2(oA, oA0, oA1);
            unpack2(oB, oB0, oB1);
            stcs_u64(out + ((size_t)(b * 8 + 2 * hp)     << 20) + i0, pack2(oA0, oB0));
            stcs_u64(out + ((size_t)(b * 8 + 2 * hp + 1) << 20) + i0, pack2(oA1, oB1));
        }
    }
}

extern "C" void kernel_launch(void* const* d_in, const int* in_sizes, int n_in,
                              void* d_out, int out_size)
{
    const float* q     = (const float*)d_in[0];
    const float* k     = (const float*)d_in[1];
    const float* masks = (const float*)d_in[2];
    const float* proj  = (const float*)d_in[3];
    const float* hw    = (const float*)d_in[4];
    const float* hb    = (const float*)d_in[5];
    float* out = (float*)d_out;

    cudaFuncSetAttribute(qk_gemm_mma, cudaFuncAttributeMaxDynamicSharedMemorySize, SM_BYTES);

    dim3 g1(N_TOK / 128, N_TOK / 128, NBG);
    qk_gemm_mma<<<g1, 256, SM_BYTES>>>(q, k);

    epilogue_kernel<<<NN / 256, 128>>>(masks, proj, hw, hb, out);
}